// round 1
// baseline (speedup 1.0000x reference)
#include <cuda_runtime.h>
#include <math.h>
#include <stdint.h>

// Problem constants (fixed by the dataset)
#define BATCH 64
#define NPRI  8732
#define NCLS  81
#define NPRIORS (BATCH * NPRI)

// Scratch (allocation-free rule: __device__ globals)
__device__ float g_neg_loss[NPRIORS];   // neg_loss (pos priors zeroed)
__device__ float g_pos_loss[BATCH];
__device__ int   g_pos_cnt[BATCH];
__device__ float g_loc_sum[BATCH];
__device__ int   g_loc_cnt[BATCH];

// ---------------------------------------------------------------------------
// Kernel 0: reset accumulators + output (graph replays must be idempotent)
// ---------------------------------------------------------------------------
__global__ void k_init(float* __restrict__ out) {
    int t = threadIdx.x;
    if (t < BATCH) {
        g_pos_loss[t] = 0.0f;
        g_pos_cnt[t]  = 0;
        g_loc_sum[t]  = 0.0f;
        g_loc_cnt[t]  = 0;
    }
    if (t == 0) out[0] = 0.0f;
}

// ---------------------------------------------------------------------------
// Kernel 1: streaming pass. One warp per prior.
//   conf_loss = lse(logits) - sum(gt_onehot * logits)
//   pos       = (gt_conf[...,0] == 0)
//   loc smooth-L1 on lanes 0..3
// ---------------------------------------------------------------------------
__global__ void __launch_bounds__(256)
k_main(const float* __restrict__ pred_conf,
       const float* __restrict__ pred_loc,
       const float* __restrict__ gt_conf,
       const float* __restrict__ gt_loc) {
    int warp = (blockIdx.x * blockDim.x + threadIdx.x) >> 5;
    int lane = threadIdx.x & 31;
    if (warp >= NPRIORS) return;

    int b = warp / NPRI;
    size_t base = (size_t)warp * NCLS;

    // lanes cover c = lane, lane+32, lane+64 (81 classes)
    int c1 = lane + 32, c2 = lane + 64;
    float l0 = pred_conf[base + lane];
    float g0 = gt_conf[base + lane];
    float l1 = -INFINITY, l2 = -INFINITY, g1 = 0.0f, g2 = 0.0f;
    if (c1 < NCLS) { l1 = pred_conf[base + c1]; g1 = gt_conf[base + c1]; }
    if (c2 < NCLS) { l2 = pred_conf[base + c2]; g2 = gt_conf[base + c2]; }

    // warp max
    float m = fmaxf(l0, fmaxf(l1, l2));
    #pragma unroll
    for (int o = 16; o; o >>= 1) m = fmaxf(m, __shfl_xor_sync(0xFFFFFFFFu, m, o));

    // warp exp-sum and target-logit sum (guard -inf*0 = NaN)
    float s  = expf(l0 - m);
    float tl = g0 * l0;
    if (c1 < NCLS) { s += expf(l1 - m); tl += g1 * l1; }
    if (c2 < NCLS) { s += expf(l2 - m); tl += g2 * l2; }
    #pragma unroll
    for (int o = 16; o; o >>= 1) {
        s  += __shfl_xor_sync(0xFFFFFFFFu, s,  o);
        tl += __shfl_xor_sync(0xFFFFFFFFu, tl, o);
    }

    float conf_loss = (m + logf(s)) - tl;       // >= 0 always
    float bg = __shfl_sync(0xFFFFFFFFu, g0, 0); // gt_conf[..., 0]
    bool  pos = (bg == 0.0f);

    // ---- localization: lanes 0..3 handle the 4 coords ----
    float locv = 0.0f;
    bool  anyloc = false;
    if (lane < 4) {
        size_t lb = (size_t)warp * 4 + lane;
        float gl = gt_loc[lb];
        if (gl != 0.0f) {
            anyloc = true;
            float d = fabsf(pred_loc[lb] - gl);
            locv = (d < 1.0f) ? 0.5f * d * d : d - 0.5f;
        }
    }
    unsigned anymask = __ballot_sync(0xFFFFFFFFu, anyloc);
    #pragma unroll
    for (int o = 16; o; o >>= 1) locv += __shfl_xor_sync(0xFFFFFFFFu, locv, o);

    if (lane == 0) {
        g_neg_loss[warp] = pos ? 0.0f : conf_loss;
        if (pos) {
            atomicAdd(&g_pos_cnt[b], 1);
            atomicAdd(&g_pos_loss[b], conf_loss);
        }
        if (anymask) {
            atomicAdd(&g_loc_cnt[b], 1);
            atomicAdd(&g_loc_sum[b], locv);
        }
    }
}

// ---------------------------------------------------------------------------
// Kernel 2: per-batch hard-negative mining (exact radix select) + final mean.
// One CTA per batch row. neg_loss values are >= 0 so uint bit order == float
// order; 4x 8-bit MSD passes give the exact k-th largest bitwise.
// ---------------------------------------------------------------------------
__global__ void __launch_bounds__(1024)
k_finish(float* __restrict__ out) {
    __shared__ unsigned sbits[NPRI];     // 34928 B
    __shared__ int hist[256];
    __shared__ int s_kk;
    __shared__ unsigned s_prefix;
    __shared__ float s_red[32];

    int b   = blockIdx.x;
    int tid = threadIdx.x;

    for (int i = tid; i < NPRI; i += blockDim.x)
        sbits[i] = __float_as_uint(g_neg_loss[b * NPRI + i]);

    int np = g_pos_cnt[b];                    // >= 1 guaranteed
    int k  = (int)((float)np * 3.0f);         // matches jnp int32 cast
    if (k > NPRI - 1) k = NPRI - 1;
    if (k < 0) k = 0;
    if (tid == 0) { s_kk = k; s_prefix = 0u; }
    __syncthreads();

    #pragma unroll
    for (int s = 24; s >= 0; s -= 8) {
        if (tid < 256) hist[tid] = 0;
        __syncthreads();
        unsigned himask = (s == 24) ? 0u : (0xFFFFFFFFu << (s + 8));
        unsigned pref   = s_prefix;
        for (int i = tid; i < NPRI; i += blockDim.x) {
            unsigned u = sbits[i];
            if ((u & himask) == pref)
                atomicAdd(&hist[(u >> s) & 0xFFu], 1);
        }
        __syncthreads();
        if (tid == 0) {
            int kk = s_kk, c = 0;
            for (int bin = 255; bin >= 0; --bin) {
                int h = hist[bin];
                if (c + h > kk) {
                    s_prefix = pref | ((unsigned)bin << s);
                    s_kk = kk - c;
                    break;
                }
                c += h;
            }
        }
        __syncthreads();
    }

    float thresh = __uint_as_float(s_prefix); // exact element value at rank k

    // sum of neg losses strictly above threshold
    float local = 0.0f;
    for (int i = tid; i < NPRI; i += blockDim.x) {
        float f = __uint_as_float(sbits[i]);
        if (f > thresh) local += f;
    }
    #pragma unroll
    for (int o = 16; o; o >>= 1) local += __shfl_xor_sync(0xFFFFFFFFu, local, o);
    if ((tid & 31) == 0) s_red[tid >> 5] = local;
    __syncthreads();
    if (tid < 32) {
        float v = (tid < (int)(blockDim.x >> 5)) ? s_red[tid] : 0.0f;
        #pragma unroll
        for (int o = 16; o; o >>= 1) v += __shfl_xor_sync(0xFFFFFFFFu, v, o);
        if (tid == 0) {
            float fnp = (float)np;
            float conf_total = g_pos_loss[b] / fnp + v / (fnp * 3.0f);
            float loc_total  = g_loc_sum[b] / (float)g_loc_cnt[b];
            atomicAdd(out, (conf_total + loc_total) * (1.0f / (float)BATCH));
        }
    }
}

// ---------------------------------------------------------------------------
extern "C" void kernel_launch(void* const* d_in, const int* in_sizes, int n_in,
                              void* d_out, int out_size) {
    const float* pred_conf = (const float*)d_in[0];
    const float* pred_loc  = (const float*)d_in[1];
    const float* gt_conf   = (const float*)d_in[2];
    const float* gt_loc    = (const float*)d_in[3];
    float* out = (float*)d_out;

    k_init<<<1, 128>>>(out);

    int warps_per_block = 256 / 32;
    int blocks = (NPRIORS + warps_per_block - 1) / warps_per_block;
    k_main<<<blocks, 256>>>(pred_conf, pred_loc, gt_conf, gt_loc);

    k_finish<<<BATCH, 1024>>>(out);
}

// round 2
// speedup vs baseline: 1.3299x; 1.3299x over previous
#include <cuda_runtime.h>
#include <math.h>
#include <stdint.h>

#define BATCH   64
#define NPRI    8732
#define NCLS    81
#define NPRIORS (BATCH * NPRI)
#define ROWS    32                  // priors per CTA in k_main
#define NCTA    (NPRIORS / ROWS)    // 17464 exactly
#define SIGNBIT 0x80000000u

// Scratch (__device__ globals: allocation-free rule)
__device__ unsigned g_conf[NPRIORS];   // conf_loss bits; sign bit = positive prior
__device__ unsigned g_locv[NPRIORS];   // loc smooth-L1 row sum bits; sign bit = row counted
__device__ float    g_batch[BATCH];
__device__ int      g_done = 0;

// ---------------------------------------------------------------------------
// Kernel 1: streaming pass. 32 rows per CTA, smem-staged, 8 threads per row.
// ---------------------------------------------------------------------------
__global__ void __launch_bounds__(256)
k_main(const float* __restrict__ pred_conf,
       const float* __restrict__ pred_loc,
       const float* __restrict__ gt_conf,
       const float* __restrict__ gt_loc) {
    __shared__ float s_conf[ROWS * NCLS];   // 10368 B
    __shared__ int   s_label[ROWS];

    int tid = threadIdx.x;
    size_t row0 = (size_t)blockIdx.x * ROWS;

    // Stage pred_conf chunk: 2592 floats = 648 float4, 16B-aligned (row0*324 % 16 == 0)
    const float4* cp = (const float4*)(pred_conf + row0 * NCLS);
    float4* sc = (float4*)s_conf;
    #pragma unroll
    for (int i = tid; i < ROWS * NCLS / 4; i += 256) sc[i] = cp[i];

    // Stream gt_conf (one-hot): find the single 1.0 per row -> label column
    const float4* gp = (const float4*)(gt_conf + row0 * NCLS);
    for (int i = tid; i < ROWS * NCLS / 4; i += 256) {
        float4 g = gp[i];
        int flat = i * 4;
        if (g.x != 0.0f) { int r = flat / NCLS;       s_label[r] = flat     - r * NCLS; }
        if (g.y != 0.0f) { int r = (flat + 1) / NCLS; s_label[r] = flat + 1 - r * NCLS; }
        if (g.z != 0.0f) { int r = (flat + 2) / NCLS; s_label[r] = flat + 2 - r * NCLS; }
        if (g.w != 0.0f) { int r = (flat + 3) / NCLS; s_label[r] = flat + 3 - r * NCLS; }
    }

    // Localization: one thread per row, float4 per row (16B-aligned)
    if (tid < ROWS) {
        size_t row = row0 + tid;
        float4 pl = ((const float4*)pred_loc)[row];
        float4 gl = ((const float4*)gt_loc)[row];
        float s = 0.0f;
        bool any = false;
        if (gl.x != 0.0f) { any = true; float d = fabsf(pl.x - gl.x); s += (d < 1.0f) ? 0.5f*d*d : d - 0.5f; }
        if (gl.y != 0.0f) { any = true; float d = fabsf(pl.y - gl.y); s += (d < 1.0f) ? 0.5f*d*d : d - 0.5f; }
        if (gl.z != 0.0f) { any = true; float d = fabsf(pl.z - gl.z); s += (d < 1.0f) ? 0.5f*d*d : d - 0.5f; }
        if (gl.w != 0.0f) { any = true; float d = fabsf(pl.w - gl.w); s += (d < 1.0f) ? 0.5f*d*d : d - 0.5f; }
        unsigned u = __float_as_uint(s);
        if (any) u |= SIGNBIT;
        g_locv[row] = u;
    }
    __syncthreads();

    // 8 threads per row: cols sub, sub+8, ..., sub+72 (+ col 80 on sub==0)
    int sub = tid & 7;
    int r   = tid >> 3;
    const float* rowp = s_conf + r * NCLS;

    float v[10];
    #pragma unroll
    for (int k = 0; k < 10; k++) v[k] = rowp[sub + 8 * k];

    float m = v[0];
    #pragma unroll
    for (int k = 1; k < 10; k++) m = fmaxf(m, v[k]);
    float vlast = 0.0f;
    if (sub == 0) { vlast = rowp[80]; m = fmaxf(m, vlast); }
    #pragma unroll
    for (int o = 4; o; o >>= 1) m = fmaxf(m, __shfl_xor_sync(0xFFFFFFFFu, m, o));

    float s = 0.0f;
    #pragma unroll
    for (int k = 0; k < 10; k++) s += __expf(v[k] - m);
    if (sub == 0) s += __expf(vlast - m);
    #pragma unroll
    for (int o = 4; o; o >>= 1) s += __shfl_xor_sync(0xFFFFFFFFu, s, o);

    if (sub == 0) {
        int lab = s_label[r];
        float tl = rowp[lab];
        float closs = fmaxf(m + __logf(s) - tl, 0.0f);  // CE >= 0; clamp fp noise
        unsigned u = __float_as_uint(closs);
        if (lab != 0) u |= SIGNBIT;                      // positive prior flag
        g_conf[row0 + r] = u;
    }
}

// ---------------------------------------------------------------------------
// Kernel 2: per-batch hard-negative mining (exact MSD radix select) + combine.
// One CTA per batch row; last finishing CTA computes the final mean.
// ---------------------------------------------------------------------------
__global__ void __launch_bounds__(1024)
k_finish(float* __restrict__ out) {
    __shared__ unsigned sbits[NPRI];       // 34928 B
    __shared__ int   hist[256];
    __shared__ float sredf[64];
    __shared__ int   sredi[64];
    __shared__ int   s_kk;
    __shared__ unsigned s_prefix;
    __shared__ int   s_np, s_loccnt;
    __shared__ float s_possum, s_locsum;
    __shared__ int   s_islast;

    int b   = blockIdx.x;
    int tid = threadIdx.x;

    // Load + classify: sign bit marks positives (conf) / counted rows (loc)
    float pos_sum = 0.0f, loc_sum = 0.0f;
    int   pos_cnt = 0,    loc_cnt = 0;
    for (int i = tid; i < NPRI; i += 1024) {
        unsigned u = g_conf[(size_t)b * NPRI + i];
        if (u & SIGNBIT) {
            pos_cnt++; pos_sum += __uint_as_float(u & ~SIGNBIT);
            u = 0u;                              // positives contribute 0 to neg array
        }
        sbits[i] = u;
        unsigned ul = g_locv[(size_t)b * NPRI + i];
        if (ul & SIGNBIT) { loc_cnt++; loc_sum += __uint_as_float(ul & ~SIGNBIT); }
    }
    // block reduce (warp then cross-warp)
    #pragma unroll
    for (int o = 16; o; o >>= 1) {
        pos_cnt += __shfl_xor_sync(0xFFFFFFFFu, pos_cnt, o);
        loc_cnt += __shfl_xor_sync(0xFFFFFFFFu, loc_cnt, o);
        pos_sum += __shfl_xor_sync(0xFFFFFFFFu, pos_sum, o);
        loc_sum += __shfl_xor_sync(0xFFFFFFFFu, loc_sum, o);
    }
    int w = tid >> 5, lane = tid & 31;
    if (lane == 0) {
        sredi[w] = pos_cnt; sredi[32 + w] = loc_cnt;
        sredf[w] = pos_sum; sredf[32 + w] = loc_sum;
    }
    __syncthreads();
    if (tid < 32) {
        int   pc = sredi[tid], lc = sredi[32 + tid];
        float ps = sredf[tid]; float ls = sredf[32 + tid];
        #pragma unroll
        for (int o = 16; o; o >>= 1) {
            pc += __shfl_xor_sync(0xFFFFFFFFu, pc, o);
            lc += __shfl_xor_sync(0xFFFFFFFFu, lc, o);
            ps += __shfl_xor_sync(0xFFFFFFFFu, ps, o);
            ls += __shfl_xor_sync(0xFFFFFFFFu, ls, o);
        }
        if (tid == 0) {
            s_np = pc; s_loccnt = lc; s_possum = ps; s_locsum = ls;
            int kk = (int)((float)pc * 3.0f);
            if (kk > NPRI - 1) kk = NPRI - 1;
            if (kk < 0) kk = 0;
            s_kk = kk;
            s_prefix = 0u;
        }
    }
    __syncthreads();

    // Exact k-th largest via 4x 8-bit MSD radix passes (values >= 0 -> uint order)
    #pragma unroll
    for (int sh = 24; sh >= 0; sh -= 8) {
        if (tid < 256) hist[tid] = 0;
        __syncthreads();
        unsigned himask = (sh == 24) ? 0u : (0xFFFFFFFFu << (sh + 8));
        unsigned pref   = s_prefix;
        for (int i = tid; i < NPRI; i += 1024) {
            unsigned u = sbits[i];
            if ((u & himask) == pref)
                atomicAdd(&hist[(u >> sh) & 0xFFu], 1);
        }
        __syncthreads();
        if (tid == 0) {
            int kk = s_kk, c = 0;
            for (int bin = 255; bin >= 0; --bin) {
                int h = hist[bin];
                if (c + h > kk) { s_prefix = pref | ((unsigned)bin << sh); s_kk = kk - c; break; }
                c += h;
            }
        }
        __syncthreads();
    }

    float thresh = __uint_as_float(s_prefix);

    // Sum of negatives strictly above threshold
    float local = 0.0f;
    for (int i = tid; i < NPRI; i += 1024) {
        float f = __uint_as_float(sbits[i]);
        if (f > thresh) local += f;
    }
    #pragma unroll
    for (int o = 16; o; o >>= 1) local += __shfl_xor_sync(0xFFFFFFFFu, local, o);
    if (lane == 0) sredf[w] = local;
    __syncthreads();
    if (tid == 0) {
        float neg = 0.0f;
        for (int i = 0; i < 32; i++) neg += sredf[i];
        float fnp = (float)s_np;
        float conf_total = s_possum / fnp + neg / (fnp * 3.0f);
        float loc_total  = s_locsum / (float)s_loccnt;
        g_batch[b] = conf_total + loc_total;
        __threadfence();
        int done = atomicAdd(&g_done, 1);
        s_islast = (done == BATCH - 1);
    }
    __syncthreads();
    if (s_islast && tid == 0) {
        float t = 0.0f;
        #pragma unroll
        for (int i = 0; i < BATCH; i++) t += g_batch[i];
        out[0] = t * (1.0f / (float)BATCH);
        g_done = 0;                         // reset for next graph replay
    }
}

// ---------------------------------------------------------------------------
extern "C" void kernel_launch(void* const* d_in, const int* in_sizes, int n_in,
                              void* d_out, int out_size) {
    const float* pred_conf = (const float*)d_in[0];
    const float* pred_loc  = (const float*)d_in[1];
    const float* gt_conf   = (const float*)d_in[2];
    const float* gt_loc    = (const float*)d_in[3];
    float* out = (float*)d_out;

    k_main<<<NCTA, 256>>>(pred_conf, pred_loc, gt_conf, gt_loc);
    k_finish<<<BATCH, 1024>>>(out);
}

// round 3
// speedup vs baseline: 1.6349x; 1.2294x over previous
#include <cuda_runtime.h>
#include <math.h>
#include <stdint.h>

#define BATCH   64
#define NPRI    8732
#define NCLS    81
#define NPRIORS (BATCH * NPRI)
#define SIGNBIT 0x80000000u

// Scratch (__device__ globals: allocation-free rule)
__device__ unsigned g_conf[NPRIORS];   // conf_loss bits; sign bit = positive prior
__device__ unsigned g_locv[NPRIORS];   // loc smooth-L1 row sum bits; sign bit = counted row
__device__ float    g_batch[BATCH];
__device__ int      g_done = 0;

// ---------------------------------------------------------------------------
// Kernel 1: streaming pass. Fully warp-autonomous: each warp owns 4 rows.
// 8 warps/CTA -> 32 rows/CTA, NPRIORS/32 CTAs. No block barriers.
// ---------------------------------------------------------------------------
__global__ void __launch_bounds__(256)
k_main(const float* __restrict__ pred_conf,
       const float* __restrict__ pred_loc,
       const float* __restrict__ gt_conf,
       const float* __restrict__ gt_loc) {
    __shared__ float s_conf[8][4 * NCLS];   // 324 floats per warp slice
    __shared__ int   s_label[8][4];

    int w    = threadIdx.x >> 5;
    int lane = threadIdx.x & 31;
    size_t row0 = ((size_t)blockIdx.x * 8 + w) * 4;   // first of this warp's 4 rows

    // Stage this warp's pred_conf rows: 324 floats = 81 float4 (16B-aligned).
    const float4* cp = (const float4*)(pred_conf + row0 * NCLS);
    float* sc = s_conf[w];
    #pragma unroll
    for (int i = lane; i < 81; i += 32)
        ((float4*)sc)[i] = cp[i];

    // Stream gt_conf (one-hot): locate the single 1.0 per row -> label column.
    const float4* gp = (const float4*)(gt_conf + row0 * NCLS);
    #pragma unroll
    for (int i = lane; i < 81; i += 32) {
        float4 g = gp[i];
        int flat = i * 4;
        if (g.x != 0.0f) { int r = flat / NCLS;       s_label[w][r] = flat     - r * NCLS; }
        if (g.y != 0.0f) { int r = (flat + 1) / NCLS; s_label[w][r] = flat + 1 - r * NCLS; }
        if (g.z != 0.0f) { int r = (flat + 2) / NCLS; s_label[w][r] = flat + 2 - r * NCLS; }
        if (g.w != 0.0f) { int r = (flat + 3) / NCLS; s_label[w][r] = flat + 3 - r * NCLS; }
    }

    // Localization: lanes 0..3, one row each (float4 per row, 16B-aligned).
    if (lane < 4) {
        size_t row = row0 + lane;
        float4 pl = ((const float4*)pred_loc)[row];
        float4 gl = ((const float4*)gt_loc)[row];
        float s = 0.0f;
        bool any = false;
        if (gl.x != 0.0f) { any = true; float d = fabsf(pl.x - gl.x); s += (d < 1.0f) ? 0.5f*d*d : d - 0.5f; }
        if (gl.y != 0.0f) { any = true; float d = fabsf(pl.y - gl.y); s += (d < 1.0f) ? 0.5f*d*d : d - 0.5f; }
        if (gl.z != 0.0f) { any = true; float d = fabsf(pl.z - gl.z); s += (d < 1.0f) ? 0.5f*d*d : d - 0.5f; }
        if (gl.w != 0.0f) { any = true; float d = fabsf(pl.w - gl.w); s += (d < 1.0f) ? 0.5f*d*d : d - 0.5f; }
        unsigned u = __float_as_uint(s);
        if (any) u |= SIGNBIT;
        g_locv[row] = u;
    }
    __syncwarp();

    // Compute: 8 threads per row (4 rows per warp). shfl offsets 4,2,1 stay
    // within each 8-lane group.
    int sub = lane & 7;
    int r   = lane >> 3;
    const float* rowp = sc + r * NCLS;

    float v[10];
    #pragma unroll
    for (int k = 0; k < 10; k++) v[k] = rowp[sub + 8 * k];

    float m = v[0];
    #pragma unroll
    for (int k = 1; k < 10; k++) m = fmaxf(m, v[k]);
    float vlast = 0.0f;
    if (sub == 0) { vlast = rowp[80]; m = fmaxf(m, vlast); }
    #pragma unroll
    for (int o = 4; o; o >>= 1) m = fmaxf(m, __shfl_xor_sync(0xFFFFFFFFu, m, o));

    float s = 0.0f;
    #pragma unroll
    for (int k = 0; k < 10; k++) s += __expf(v[k] - m);
    if (sub == 0) s += __expf(vlast - m);
    #pragma unroll
    for (int o = 4; o; o >>= 1) s += __shfl_xor_sync(0xFFFFFFFFu, s, o);

    if (sub == 0) {
        int lab = s_label[w][r];
        float tl = rowp[lab];
        float closs = fmaxf(m + __logf(s) - tl, 0.0f);  // CE >= 0; clamp fp noise
        unsigned u = __float_as_uint(closs);
        if (lab != 0) u |= SIGNBIT;                      // positive-prior flag
        g_conf[row0 + r] = u;
    }
}

// ---------------------------------------------------------------------------
// Warp-parallel bin select for MSD radix pass. Called by tid<32 only.
// Finds bin b with suffixcount(b+1) <= kk < suffixcount(b), updates prefix/kk.
// ---------------------------------------------------------------------------
__device__ __forceinline__ void select_bin(const int* hist, int sh,
                                           unsigned* s_prefix, int* s_kk,
                                           int lane) {
    int kk = *s_kk;
    unsigned pref = *s_prefix;
    int base = lane * 8;
    int h[8];
    int T = 0;
    #pragma unroll
    for (int j = 0; j < 8; j++) { h[j] = hist[base + j]; T += h[j]; }
    // inclusive suffix-sum across lanes (lane..31)
    int ssum = T;
    #pragma unroll
    for (int o = 1; o < 32; o <<= 1) {
        int vv = __shfl_down_sync(0xFFFFFFFFu, ssum, o);
        if (lane + o < 32) ssum += vv;
    }
    int excl = ssum - T;                     // count in bins above this lane's range
    if (excl <= kk && kk < ssum) {           // target bin lives in this lane
        int c = excl;
        #pragma unroll
        for (int j = 7; j >= 0; j--) {
            if (c + h[j] > kk) {
                *s_prefix = pref | ((unsigned)(base + j) << sh);
                *s_kk = kk - c;
                break;
            }
            c += h[j];
        }
    }
}

// ---------------------------------------------------------------------------
// Kernel 2: per-batch hard-negative mining (exact MSD radix select) + combine.
// One CTA per batch row; last finishing CTA computes the final mean.
// ---------------------------------------------------------------------------
__global__ void __launch_bounds__(1024)
k_finish(float* __restrict__ out) {
    __shared__ unsigned sbits[NPRI];       // 34928 B
    __shared__ int   hist[256];
    __shared__ float sredf[64];
    __shared__ int   sredi[64];
    __shared__ int   s_kk;
    __shared__ unsigned s_prefix;
    __shared__ int   s_np, s_loccnt;
    __shared__ float s_possum, s_locsum;
    __shared__ int   s_islast;

    int b   = blockIdx.x;
    int tid = threadIdx.x;
    int w = tid >> 5, lane = tid & 31;

    if (tid < 256) hist[tid] = 0;
    __syncthreads();

    // Load + classify + histogram of top byte (radix pass 1 fused with load).
    float pos_sum = 0.0f, loc_sum = 0.0f;
    int   pos_cnt = 0,    loc_cnt = 0;
    for (int i = tid; i < NPRI; i += 1024) {
        unsigned u = g_conf[(size_t)b * NPRI + i];
        if (u & SIGNBIT) {
            pos_cnt++; pos_sum += __uint_as_float(u & ~SIGNBIT);
            u = 0u;                              // positives contribute 0 to neg array
        }
        sbits[i] = u;
        atomicAdd(&hist[u >> 24], 1);
        unsigned ul = g_locv[(size_t)b * NPRI + i];
        if (ul & SIGNBIT) { loc_cnt++; loc_sum += __uint_as_float(ul & ~SIGNBIT); }
    }
    // block reduce pos/loc stats
    #pragma unroll
    for (int o = 16; o; o >>= 1) {
        pos_cnt += __shfl_xor_sync(0xFFFFFFFFu, pos_cnt, o);
        loc_cnt += __shfl_xor_sync(0xFFFFFFFFu, loc_cnt, o);
        pos_sum += __shfl_xor_sync(0xFFFFFFFFu, pos_sum, o);
        loc_sum += __shfl_xor_sync(0xFFFFFFFFu, loc_sum, o);
    }
    if (lane == 0) {
        sredi[w] = pos_cnt; sredi[32 + w] = loc_cnt;
        sredf[w] = pos_sum; sredf[32 + w] = loc_sum;
    }
    __syncthreads();
    if (tid < 32) {
        int   pc = sredi[tid], lc = sredi[32 + tid];
        float ps = sredf[tid]; float ls = sredf[32 + tid];
        #pragma unroll
        for (int o = 16; o; o >>= 1) {
            pc += __shfl_xor_sync(0xFFFFFFFFu, pc, o);
            lc += __shfl_xor_sync(0xFFFFFFFFu, lc, o);
            ps += __shfl_xor_sync(0xFFFFFFFFu, ps, o);
            ls += __shfl_xor_sync(0xFFFFFFFFu, ls, o);
        }
        if (tid == 0) {
            s_np = pc; s_loccnt = lc; s_possum = ps; s_locsum = ls;
            int kk = (int)((float)pc * 3.0f);
            if (kk > NPRI - 1) kk = NPRI - 1;
            if (kk < 0) kk = 0;
            s_kk = kk;
            s_prefix = 0u;
        }
    }
    __syncthreads();

    // Radix pass 1 select (histogram already built during load).
    if (tid < 32) select_bin(hist, 24, &s_prefix, &s_kk, lane);
    __syncthreads();

    // Radix passes 2..4.
    #pragma unroll
    for (int sh = 16; sh >= 0; sh -= 8) {
        if (tid < 256) hist[tid] = 0;
        __syncthreads();
        unsigned himask = 0xFFFFFFFFu << (sh + 8);
        unsigned pref   = s_prefix;
        for (int i = tid; i < NPRI; i += 1024) {
            unsigned u = sbits[i];
            if ((u & himask) == pref)
                atomicAdd(&hist[(u >> sh) & 0xFFu], 1);
        }
        __syncthreads();
        if (tid < 32) select_bin(hist, sh, &s_prefix, &s_kk, lane);
        __syncthreads();
    }

    float thresh = __uint_as_float(s_prefix);   // exact value at rank k

    // Sum of negatives strictly above threshold.
    float local = 0.0f;
    for (int i = tid; i < NPRI; i += 1024) {
        float f = __uint_as_float(sbits[i]);
        if (f > thresh) local += f;
    }
    #pragma unroll
    for (int o = 16; o; o >>= 1) local += __shfl_xor_sync(0xFFFFFFFFu, local, o);
    if (lane == 0) sredf[w] = local;
    __syncthreads();
    if (tid < 32) {
        float vv = sredf[tid];
        #pragma unroll
        for (int o = 16; o; o >>= 1) vv += __shfl_xor_sync(0xFFFFFFFFu, vv, o);
        if (tid == 0) {
            float fnp = (float)s_np;
            float conf_total = s_possum / fnp + vv / (fnp * 3.0f);
            float loc_total  = s_locsum / (float)s_loccnt;
            g_batch[b] = conf_total + loc_total;
            __threadfence();
            int done = atomicAdd(&g_done, 1);
            s_islast = (done == BATCH - 1);
        }
    }
    __syncthreads();
    if (s_islast && tid < 32) {
        float t = (tid < BATCH/2) ? (g_batch[tid] + g_batch[tid + 32]) : 0.0f;
        t = g_batch[tid] + g_batch[tid + 32];
        #pragma unroll
        for (int o = 16; o; o >>= 1) t += __shfl_xor_sync(0xFFFFFFFFu, t, o);
        if (tid == 0) {
            out[0] = t * (1.0f / (float)BATCH);
            g_done = 0;                          // reset for next graph replay
        }
    }
}

// ---------------------------------------------------------------------------
extern "C" void kernel_launch(void* const* d_in, const int* in_sizes, int n_in,
                              void* d_out, int out_size) {
    const float* pred_conf = (const float*)d_in[0];
    const float* pred_loc  = (const float*)d_in[1];
    const float* gt_conf   = (const float*)d_in[2];
    const float* gt_loc    = (const float*)d_in[3];
    float* out = (float*)d_out;

    k_main<<<NPRIORS / 32, 256>>>(pred_conf, pred_loc, gt_conf, gt_loc);
    k_finish<<<BATCH, 1024>>>(out);
}